// round 6
// baseline (speedup 1.0000x reference)
#include <cuda_runtime.h>

// Volume rendering (NeRF-style) on GB300 — R6: 2 rays per warp, all loads
// front-batched (MLP_p1 10). The two rays' shfl-scan chains are independent
// and interleave, halving exposed scan latency and deepening the per-warp
// load burst. Streaming (.cs) hints retained from R4 (98.1 -> 96.3 us).
//
// Inputs (metadata order): rgb [N,128,3] f32, density [N,128,1] f32,
//                          distances [N,128] f32. Output: [N,3] f32.
//
// Per ray:
//   delta_i  = t_{i+1} - t_i   (last sample: 1e10)
//   omega_i  = exp(-density_i * delta_i)      (= 1 - alpha_i)
//   T_i      = exclusive cumprod(omega)       (warp shfl scan)
//   weight_i = (1 - omega_i) * T_i
//   out      = sum_i weight_i * rgb_i

#ifndef FULL_MASK
#define FULL_MASK 0xffffffffu
#endif

static constexpr int N_SAMPLES = 128;
static constexpr float FAR_DELTA = 1e10f;
static constexpr int RAYS_PER_WARP = 2;
static constexpr int WARPS_PER_BLOCK = 8;

__global__ void __launch_bounds__(WARPS_PER_BLOCK * 32)
volrend_kernel(const float* __restrict__ rgb,
               const float* __restrict__ density,
               const float* __restrict__ dist,
               float* __restrict__ out,
               int n_rays)
{
    const int warp_idx = (blockIdx.x * blockDim.x + threadIdx.x) >> 5;
    const int lane     = threadIdx.x & 31;
    const int rayA = warp_idx * RAYS_PER_WARP;
    const int rayB = rayA + 1;
    if (rayA >= n_rays) return;

    const long baseA = (long)rayA * N_SAMPLES;
    const long baseB = (long)rayB * N_SAMPLES;

    // ---- front-batched streaming loads: 10 x LDG.128 ----
    const float4 dA = __ldcs(reinterpret_cast<const float4*>(dist    + baseA) + lane);
    const float4 dB = __ldcs(reinterpret_cast<const float4*>(dist    + baseB) + lane);
    const float4 sA = __ldcs(reinterpret_cast<const float4*>(density + baseA) + lane);
    const float4 sB = __ldcs(reinterpret_cast<const float4*>(density + baseB) + lane);
    const float4* rgbA = reinterpret_cast<const float4*>(rgb + baseA * 3) + lane * 3;
    const float4* rgbB = reinterpret_cast<const float4*>(rgb + baseB * 3) + lane * 3;
    const float4 a0 = __ldcs(rgbA + 0);
    const float4 a1 = __ldcs(rgbA + 1);
    const float4 a2 = __ldcs(rgbA + 2);
    const float4 b0 = __ldcs(rgbB + 0);
    const float4 b1 = __ldcs(rgbB + 1);
    const float4 b2 = __ldcs(rgbB + 2);

    // ---- deltas ----
    const float dA_next = __shfl_down_sync(FULL_MASK, dA.x, 1);
    const float dB_next = __shfl_down_sync(FULL_MASK, dB.x, 1);
    const float aL0 = dA.y - dA.x, aL1 = dA.z - dA.y, aL2 = dA.w - dA.z;
    const float aL3 = (lane == 31) ? FAR_DELTA : (dA_next - dA.w);
    const float bL0 = dB.y - dB.x, bL1 = dB.z - dB.y, bL2 = dB.w - dB.z;
    const float bL3 = (lane == 31) ? FAR_DELTA : (dB_next - dB.w);

    // ---- omega = exp(-sigma * delta) ----
    const float aw0 = __expf(-sA.x * aL0);
    const float aw1 = __expf(-sA.y * aL1);
    const float aw2 = __expf(-sA.z * aL2);
    const float aw3 = __expf(-sA.w * aL3);
    const float bw0 = __expf(-sB.x * bL0);
    const float bw1 = __expf(-sB.y * bL1);
    const float bw2 = __expf(-sB.z * bL2);
    const float bw3 = __expf(-sB.w * bL3);

    // ---- two independent exclusive-cumprod scans (interleaved by ILP) ----
    float inclA = aw0 * aw1 * aw2 * aw3;
    float inclB = bw0 * bw1 * bw2 * bw3;
    #pragma unroll
    for (int off = 1; off < 32; off <<= 1) {
        const float vA = __shfl_up_sync(FULL_MASK, inclA, off);
        const float vB = __shfl_up_sync(FULL_MASK, inclB, off);
        if (lane >= off) { inclA *= vA; inclB *= vB; }
    }
    float TA = __shfl_up_sync(FULL_MASK, inclA, 1);
    float TB = __shfl_up_sync(FULL_MASK, inclB, 1);
    if (lane == 0) { TA = 1.0f; TB = 1.0f; }

    // ---- local weights ----
    const float at0 = TA, at1 = at0 * aw0, at2 = at1 * aw1, at3 = at2 * aw2;
    const float awt0 = at0 - at1, awt1 = at1 - at2, awt2 = at2 - at3;
    const float awt3 = at3 * (1.0f - aw3);
    const float bt0 = TB, bt1 = bt0 * bw0, bt2 = bt1 * bw1, bt3 = bt2 * bw2;
    const float bwt0 = bt0 - bt1, bwt1 = bt1 - bt2, bwt2 = bt2 - bt3;
    const float bwt3 = bt3 * (1.0f - bw3);

    // rgb layout per lane: s0=(c0.x,c0.y,c0.z) s1=(c0.w,c1.x,c1.y)
    //                      s2=(c1.z,c1.w,c2.x) s3=(c2.y,c2.z,c2.w)
    float arR = awt0 * a0.x + awt1 * a0.w + awt2 * a1.z + awt3 * a2.y;
    float arG = awt0 * a0.y + awt1 * a1.x + awt2 * a1.w + awt3 * a2.z;
    float arB = awt0 * a0.z + awt1 * a1.y + awt2 * a2.x + awt3 * a2.w;
    float brR = bwt0 * b0.x + bwt1 * b0.w + bwt2 * b1.z + bwt3 * b2.y;
    float brG = bwt0 * b0.y + bwt1 * b1.x + bwt2 * b1.w + bwt3 * b2.z;
    float brB = bwt0 * b0.z + bwt1 * b1.y + bwt2 * b2.x + bwt3 * b2.w;

    // ---- warp reductions (both rays interleaved) ----
    #pragma unroll
    for (int off = 16; off > 0; off >>= 1) {
        arR += __shfl_xor_sync(FULL_MASK, arR, off);
        brR += __shfl_xor_sync(FULL_MASK, brR, off);
        arG += __shfl_xor_sync(FULL_MASK, arG, off);
        brG += __shfl_xor_sync(FULL_MASK, brG, off);
        arB += __shfl_xor_sync(FULL_MASK, arB, off);
        brB += __shfl_xor_sync(FULL_MASK, brB, off);
    }

    if (lane == 0) {
        float* o = out + (long)rayA * 3;
        o[0] = arR; o[1] = arG; o[2] = arB;
        o[3] = brR; o[4] = brG; o[5] = brB;
    }
}

extern "C" void kernel_launch(void* const* d_in, const int* in_sizes, int n_in,
                              void* d_out, int out_size)
{
    const float* rgb     = (const float*)d_in[0];
    const float* density = (const float*)d_in[1];
    const float* dist    = (const float*)d_in[2];
    float* out = (float*)d_out;

    const int n_rays = in_sizes[2] / N_SAMPLES;   // distances: [N, 128]

    const int threads = WARPS_PER_BLOCK * 32;
    const int rays_per_block = WARPS_PER_BLOCK * RAYS_PER_WARP;
    const int blocks = (n_rays + rays_per_block - 1) / rays_per_block;

    volrend_kernel<<<blocks, threads>>>(rgb, density, dist, out, n_rays);
}